// round 12
// baseline (speedup 1.0000x reference)
#include <cuda_runtime.h>
#include <cstdint>

#define T_STEPS 256
#define BATCH   64
#define HID     512
#define OUTD    4

#define CLUSTER 8          // CTAs per cluster
#define RPC     4          // batch rows per cluster
#define CPC     64         // hidden columns per CTA

// Global scratch (no cudaMalloc allowed)
__device__ __align__(16) float g_xw[T_STEPS * BATCH * HID];   // [T][B][H]

__device__ __forceinline__ uint32_t smem_u32(const void* p) {
    uint32_t a;
    asm("{ .reg .u64 t; cvta.to.shared.u64 t, %1; cvt.u32.u64 %0, t; }"
        : "=r"(a) : "l"(p));
    return a;
}
__device__ __forceinline__ uint32_t mapa32(uint32_t a, int r) {
    uint32_t ra;
    asm("mapa.shared::cluster.u32 %0, %1, %2;" : "=r"(ra) : "r"(a), "r"(r));
    return ra;
}
__device__ __forceinline__ void mbar_init(uint32_t a, uint32_t cnt) {
    asm volatile("mbarrier.init.shared.b64 [%0], %1;" :: "r"(a), "r"(cnt) : "memory");
}
__device__ __forceinline__ void mbar_expect(uint32_t a, uint32_t bytes) {
    asm volatile("mbarrier.arrive.expect_tx.shared.b64 _, [%0], %1;"
                 :: "r"(a), "r"(bytes) : "memory");
}
// One-way remote 8-byte store that signals the remote mbarrier's tx count.
__device__ __forceinline__ void st_async_b64(uint32_t rdst, unsigned long long v,
                                             uint32_t rbar) {
    asm volatile("st.async.shared::cluster.mbarrier::complete_tx::bytes.b64 [%0], %1, [%2];"
                 :: "r"(rdst), "l"(v), "r"(rbar) : "memory");
}
__device__ __forceinline__ void mbar_wait(uint32_t a, uint32_t parity) {
    asm volatile("{\n\t.reg .pred P;\n\t"
                 "WL%=:\n\t"
                 "mbarrier.try_wait.parity.acquire.cluster.shared::cta.b64 P, [%0], %1;\n\t"
                 "@P bra WD%=;\n\t"
                 "bra WL%=;\n\t"
                 "WD%=:\n\t}"
                 :: "r"(a), "r"(parity) : "memory");
}
__device__ __forceinline__ unsigned long long fma2(unsigned long long a,
                                                   unsigned long long b,
                                                   unsigned long long c) {
    unsigned long long d;
    asm("fma.rn.f32x2 %0, %1, %2, %3;" : "=l"(d) : "l"(a), "l"(b), "l"(c));
    return d;
}
__device__ __forceinline__ float f32x2_hsum(unsigned long long a,
                                            unsigned long long b) {
    unsigned long long s;
    asm("add.rn.f32x2 %0, %1, %2;" : "=l"(s) : "l"(a), "l"(b));
    unsigned int lo, hi;
    asm("mov.b64 {%0, %1}, %2;" : "=r"(lo), "=r"(hi) : "l"(s));
    return __uint_as_float(lo) + __uint_as_float(hi);
}
__device__ __forceinline__ unsigned long long pack2(float x, float y) {
    unsigned long long v;
    asm("mov.b64 %0, {%1, %2};" : "=l"(v) : "r"(__float_as_uint(x)), "r"(__float_as_uint(y)));
    return v;
}

// Accurate even under --use_fast_math (expf -> __expf ~2^-21 rel error).
__device__ __forceinline__ float tanh_accurate(float z) {
    return 1.0f - 2.0f / (expf(2.0f * z) + 1.0f);
}

// ---------------------------------------------------------------------------
// Kernel 1: g_xw[t][b][:] = emb[x[b][t]] @ W_ih^T + b_ih
// 128x128 tile, BK=8, 256 threads, 8x8 microtile, register-prefetch pipeline.
// ---------------------------------------------------------------------------
__global__ void __launch_bounds__(256)
proj_kernel(const int* __restrict__ x,
            const float* __restrict__ emb,
            const float* __restrict__ W_ih,
            const float* __restrict__ b_ih)
{
    __shared__ float As[8][128];
    __shared__ float Bs[8][128];
    __shared__ int   idx[128];

    const int tid = threadIdx.x;
    const int m0 = blockIdx.y * 128;
    const int j0 = blockIdx.x * 128;

    if (tid < 128) idx[tid] = x[m0 + tid];
    __syncthreads();

    const int lrow = tid >> 1;
    const int lq   = tid & 1;
    const int ty = tid >> 4;
    const int tx = tid & 15;

    const size_t arow = (size_t)idx[lrow] * HID;
    const size_t brow = (size_t)(j0 + lrow) * HID;

    float acc[8][8];
#pragma unroll
    for (int i = 0; i < 8; ++i)
#pragma unroll
        for (int jc = 0; jc < 8; ++jc) acc[i][jc] = 0.0f;

    float4 av = *(const float4*)(emb  + arow + 4 * lq);
    float4 bv = *(const float4*)(W_ih + brow + 4 * lq);

    for (int k0 = 0; k0 < HID; k0 += 8) {
        As[4*lq+0][lrow] = av.x; As[4*lq+1][lrow] = av.y;
        As[4*lq+2][lrow] = av.z; As[4*lq+3][lrow] = av.w;
        Bs[4*lq+0][lrow] = bv.x; Bs[4*lq+1][lrow] = bv.y;
        Bs[4*lq+2][lrow] = bv.z; Bs[4*lq+3][lrow] = bv.w;
        __syncthreads();

        if (k0 + 8 < HID) {
            av = *(const float4*)(emb  + arow + k0 + 8 + 4 * lq);
            bv = *(const float4*)(W_ih + brow + k0 + 8 + 4 * lq);
        }

#pragma unroll
        for (int k = 0; k < 8; ++k) {
            float a[8], b[8];
            *(float4*)(a)     = *(const float4*)(&As[k][8 * ty]);
            *(float4*)(a + 4) = *(const float4*)(&As[k][8 * ty + 4]);
            *(float4*)(b)     = *(const float4*)(&Bs[k][8 * tx]);
            *(float4*)(b + 4) = *(const float4*)(&Bs[k][8 * tx + 4]);
#pragma unroll
            for (int i = 0; i < 8; ++i)
#pragma unroll
                for (int jc = 0; jc < 8; ++jc)
                    acc[i][jc] += a[i] * b[jc];
        }
        __syncthreads();
    }

    float bi[8];
    *(float4*)(bi)     = *(const float4*)(b_ih + j0 + 8 * tx);
    *(float4*)(bi + 4) = *(const float4*)(b_ih + j0 + 8 * tx + 4);

#pragma unroll
    for (int i = 0; i < 8; ++i) {
        int m = m0 + 8 * ty + i;
        int b = m >> 8;      // T = 256
        int t = m & 255;
        float* dst = &g_xw[((size_t)t * BATCH + b) * HID + j0 + 8 * tx];
        float4 v0, v1;
        v0.x = acc[i][0] + bi[0]; v0.y = acc[i][1] + bi[1];
        v0.z = acc[i][2] + bi[2]; v0.w = acc[i][3] + bi[3];
        v1.x = acc[i][4] + bi[4]; v1.y = acc[i][5] + bi[5];
        v1.z = acc[i][6] + bi[6]; v1.w = acc[i][7] + bi[7];
        *(float4*)(dst)     = v0;
        *(float4*)(dst + 4) = v1;
    }
}

// ---------------------------------------------------------------------------
// Kernel 2: recurrence + FC. 16 clusters x 8 CTAs x 512 threads.
// Compute: thread (j2 = tid&31, kc = tid>>5) as R10.
// Reduce: tid<256 (8 warps). Unit u = tid&127 (row u>>5, colpair u&31);
// lower half (tid<128) pushes its b64 to peers 0-3, upper half to peers 4-7.
// Redundant reduction is bit-identical, so both halves push the same value.
// Barrier: compute-only threads bar.arrive (non-blocking), reducers bar.sync.
// ---------------------------------------------------------------------------
#define RNN_STEP(T, RB, WB, PHVAR, DOWAIT)                                    \
do {                                                                          \
    if (tid == 0) mbar_expect(barA + 8 * (WB), 8192u);                        \
    float2 xw2 = make_float2(0.0f, 0.0f);                                     \
    if (tid < 256)                                                            \
        xw2 = *(const float2*)&g_xw[((size_t)(T) * BATCH + (r0 + rr)) * HID   \
                                    + j0 + 2 * jj2];                          \
    if (DOWAIT) { mbar_wait(barA + 8 * (RB), PHVAR); PHVAR ^= 1u; }           \
    _Pragma("unroll")                                                         \
    for (int r = 0; r < RPC; ++r) {                                           \
        const ulonglong2* hrow = (const ulonglong2*)                          \
            (&hs[RB][kc >> 1][r][(kc & 1) * 32]);                             \
        unsigned long long a0 = 0ull, b0 = 0ull, a1 = 0ull, b1 = 0ull;        \
        _Pragma("unroll")                                                     \
        for (int q = 0; q < 8; ++q) {                                         \
            ulonglong2 hv = hrow[q];                                          \
            a0 = fma2(hv.x, wp0[2*q],   a0);                                  \
            b0 = fma2(hv.y, wp0[2*q+1], b0);                                  \
            a1 = fma2(hv.x, wp1[2*q],   a1);                                  \
            b1 = fma2(hv.y, wp1[2*q+1], b1);                                  \
        }                                                                     \
        *(float2*)&psum[r][kc][2 * j2] =                                      \
            make_float2(f32x2_hsum(a0, b0), f32x2_hsum(a1, b1));              \
    }                                                                         \
    if (tid < 256) {                                                          \
        asm volatile("bar.sync 1, 512;" ::: "memory");                        \
        float z0 = bhh2.x + xw2.x;                                            \
        float z1 = bhh2.y + xw2.y;                                            \
        _Pragma("unroll")                                                     \
        for (int c = 0; c < 16; ++c) {                                        \
            float2 pv = *(const float2*)&psum[rr][c][2 * jj2];                \
            z0 += pv.x; z1 += pv.y;                                           \
        }                                                                     \
        const unsigned long long hpk =                                        \
            pack2(tanh_accurate(z0), tanh_accurate(z1));                      \
        const uint32_t loff = hsA +                                           \
            (uint32_t)((((WB) * CLUSTER + rank) * RPC + rr) * 64 + 2 * jj2)   \
            * 4u;                                                             \
        const uint32_t lbar = barA + 8 * (WB);                                \
        _Pragma("unroll")                                                     \
        for (int c = 0; c < 4; ++c) {                                         \
            const int peer = phalf + c;                                       \
            st_async_b64(mapa32(loff, peer), hpk, mapa32(lbar, peer));        \
        }                                                                     \
    } else {                                                                  \
        asm volatile("bar.arrive 1, 512;" ::: "memory");                      \
    }                                                                         \
} while (0)

__global__ void __cluster_dims__(CLUSTER, 1, 1) __launch_bounds__(512, 1)
rec_kernel(const float* __restrict__ W_hh,
           const float* __restrict__ b_hh,
           const float* __restrict__ W_fc,
           const float* __restrict__ b_fc,
           float* __restrict__ out)
{
    __shared__ __align__(16) float hs[2][CLUSTER][RPC][64];   // 16 KB
    __shared__ __align__(16) float psum[RPC][16][64];         // 16 KB
    __shared__ __align__(8)  unsigned long long mbar[2];

    const int tid  = threadIdx.x;
    const int rank = blockIdx.x & (CLUSTER - 1);
    const int cl   = blockIdx.x / CLUSTER;
    const int r0 = cl * RPC;
    const int j0 = rank * CPC;

    const int j2  = tid & 31;          // compute: column pair (cols 2j2, 2j2+1)
    const int kc  = tid >> 5;          // compute: 32-wide k chunk (0..15)
    const int rr  = (tid >> 5) & 3;    // reduce (tid<256): row 0..3
    const int jj2 = tid & 31;          // reduce: column pair
    const int phalf = (tid >> 7) << 2; // reduce: peer group base (0 or 4)

    const uint32_t hsA  = smem_u32(hs);
    const uint32_t barA = smem_u32(mbar);

    // W_hh slices for 2 columns, packed as f32x2 k-pairs (16 u64 each).
    unsigned long long wp0[16], wp1[16];
    {
        const float* w0 = W_hh + (size_t)(j0 + 2 * j2)     * HID + kc * 32;
        const float* w1 = W_hh + (size_t)(j0 + 2 * j2 + 1) * HID + kc * 32;
#pragma unroll
        for (int q = 0; q < 8; ++q) {
            ulonglong2 v0 = *(const ulonglong2*)(w0 + 4 * q);
            ulonglong2 v1 = *(const ulonglong2*)(w1 + 4 * q);
            wp0[2*q] = v0.x; wp0[2*q+1] = v0.y;
            wp1[2*q] = v1.x; wp1[2*q+1] = v1.y;
        }
    }
    float2 bhh2 = make_float2(0.0f, 0.0f);
    if (tid < 256) bhh2 = *(const float2*)&b_hh[j0 + 2 * jj2];

    // Init: two mbarriers (1 arrival each = tid0's expect_tx) + h0 = 0.
    if (tid == 0) { mbar_init(barA, 1u); mbar_init(barA + 8, 1u); }
    for (int i = tid; i < CLUSTER * RPC * 64; i += 512)
        (&hs[0][0][0][0])[i] = 0.0f;
    __syncthreads();
    // Peers' barriers must be initialized before any st.async reaches them.
    asm volatile("barrier.cluster.arrive.aligned;" ::: "memory");
    asm volatile("barrier.cluster.wait.aligned;"   ::: "memory");

    uint32_t ph0 = 0, ph1 = 0;

    // Step 1: reads local zeros in hs[0] (no wait), writes hs[1]/bar1.
    RNN_STEP(0, 0, 1, ph1, false);
    // Step 2: waits bar1, writes hs[0]/bar0.
    RNN_STEP(1, 1, 0, ph1, true);
    // Steps 3..256 in pairs.
#pragma unroll 1
    for (int q = 1; q < 128; ++q) {
        RNN_STEP(2 * q,     0, 1, ph0, true);   // odd step
        RNN_STEP(2 * q + 1, 1, 0, ph1, true);   // even step
    }

    // Consume the step-256 pushes (buffer 0).
    mbar_wait(barA, ph0);

    // FC: h_T in hs[0]; h[r][k] = hs[0][k>>6][r][k&63]. Warp w: r=w>>2, o=w&3.
    if (rank == 0) {
        const int w    = tid >> 5;
        const int lane = tid & 31;
        const int r = w >> 2;
        const int o = w & 3;
        float s = 0.0f;
        const float* wf = W_fc + (size_t)o * HID;
#pragma unroll
        for (int k = lane; k < HID; k += 32)
            s += hs[0][k >> 6][r][k & 63] * wf[k];
#pragma unroll
        for (int sh = 16; sh > 0; sh >>= 1)
            s += __shfl_xor_sync(0xFFFFFFFFu, s, sh);
        if (lane == 0)
            out[(r0 + r) * OUTD + o] = s + b_fc[o];
    }

    // Cluster-wide quiesce before exit (DSMEM lifetime).
    asm volatile("barrier.cluster.arrive.aligned;" ::: "memory");
    asm volatile("barrier.cluster.wait.aligned;"   ::: "memory");
}

extern "C" void kernel_launch(void* const* d_in, const int* in_sizes, int n_in,
                              void* d_out, int out_size)
{
    const int*   x    = (const int*)  d_in[0];
    const float* emb  = (const float*)d_in[1];
    const float* W_ih = (const float*)d_in[2];
    const float* W_hh = (const float*)d_in[3];
    const float* b_ih = (const float*)d_in[4];
    const float* b_hh = (const float*)d_in[5];
    const float* W_fc = (const float*)d_in[6];
    const float* b_fc = (const float*)d_in[7];
    float* out = (float*)d_out;
    (void)in_sizes; (void)n_in; (void)out_size;

    proj_kernel<<<dim3(HID / 128, (BATCH * T_STEPS) / 128), 256>>>(x, emb, W_ih, b_ih);
    rec_kernel<<<(BATCH / RPC) * CLUSTER, 512>>>(W_hh, b_hh, W_fc, b_fc, out);
}

// round 13
// speedup vs baseline: 1.2211x; 1.2211x over previous
#include <cuda_runtime.h>
#include <cstdint>

#define T_STEPS 256
#define BATCH   64
#define HID     512
#define OUTD    4

#define CLUSTER 8          // CTAs per cluster
#define RPC     4          // batch rows per group
#define GROUPS  2          // interleaved groups per cluster (8 rows total)
#define CPC     64         // hidden columns per CTA

// Shared-memory float layout (dynamic):
//   hs:   grp*4096 + buf*2048 + rank*256 + row*64 + col        [0, 8192)
//   psum: PS_OFF + grp*4096 + row*1024 + kc*64 + col           [8192, 16384)
//   mbar: byte offset 65536, 4 barriers (grp*2 + buf)
#define PS_OFF 8192
#define SMEM_BYTES (16384 * 4 + 32)

// Global scratch (no cudaMalloc allowed)
__device__ __align__(16) float g_xw[T_STEPS * BATCH * HID];   // [T][B][H]

__device__ __forceinline__ uint32_t smem_u32(const void* p) {
    uint32_t a;
    asm("{ .reg .u64 t; cvta.to.shared.u64 t, %1; cvt.u32.u64 %0, t; }"
        : "=r"(a) : "l"(p));
    return a;
}
__device__ __forceinline__ uint32_t mapa32(uint32_t a, int r) {
    uint32_t ra;
    asm("mapa.shared::cluster.u32 %0, %1, %2;" : "=r"(ra) : "r"(a), "r"(r));
    return ra;
}
__device__ __forceinline__ void mbar_init(uint32_t a, uint32_t cnt) {
    asm volatile("mbarrier.init.shared.b64 [%0], %1;" :: "r"(a), "r"(cnt) : "memory");
}
__device__ __forceinline__ void mbar_expect(uint32_t a, uint32_t bytes) {
    asm volatile("mbarrier.arrive.expect_tx.shared.b64 _, [%0], %1;"
                 :: "r"(a), "r"(bytes) : "memory");
}
// One-way remote 8-byte store that signals the remote mbarrier's tx count.
__device__ __forceinline__ void st_async_b64(uint32_t rdst, unsigned long long v,
                                             uint32_t rbar) {
    asm volatile("st.async.shared::cluster.mbarrier::complete_tx::bytes.b64 [%0], %1, [%2];"
                 :: "r"(rdst), "l"(v), "r"(rbar) : "memory");
}
__device__ __forceinline__ void mbar_wait(uint32_t a, uint32_t parity) {
    asm volatile("{\n\t.reg .pred P;\n\t"
                 "WL%=:\n\t"
                 "mbarrier.try_wait.parity.acquire.cluster.shared::cta.b64 P, [%0], %1;\n\t"
                 "@P bra WD%=;\n\t"
                 "bra WL%=;\n\t"
                 "WD%=:\n\t}"
                 :: "r"(a), "r"(parity) : "memory");
}
__device__ __forceinline__ unsigned long long fma2(unsigned long long a,
                                                   unsigned long long b,
                                                   unsigned long long c) {
    unsigned long long d;
    asm("fma.rn.f32x2 %0, %1, %2, %3;" : "=l"(d) : "l"(a), "l"(b), "l"(c));
    return d;
}
__device__ __forceinline__ float f32x2_hsum(unsigned long long a,
                                            unsigned long long b) {
    unsigned long long s;
    asm("add.rn.f32x2 %0, %1, %2;" : "=l"(s) : "l"(a), "l"(b));
    unsigned int lo, hi;
    asm("mov.b64 {%0, %1}, %2;" : "=r"(lo), "=r"(hi) : "l"(s));
    return __uint_as_float(lo) + __uint_as_float(hi);
}
__device__ __forceinline__ unsigned long long pack2(float x, float y) {
    unsigned long long v;
    asm("mov.b64 %0, {%1, %2};" : "=l"(v) : "r"(__float_as_uint(x)), "r"(__float_as_uint(y)));
    return v;
}

// Accurate even under --use_fast_math (expf -> __expf ~2^-21 rel error).
__device__ __forceinline__ float tanh_accurate(float z) {
    return 1.0f - 2.0f / (expf(2.0f * z) + 1.0f);
}

// ---------------------------------------------------------------------------
// Kernel 1: g_xw[t][b][:] = emb[x[b][t]] @ W_ih^T + b_ih
// 128x128 tile, BK=8, 256 threads, 8x8 microtile, register-prefetch pipeline.
// ---------------------------------------------------------------------------
__global__ void __launch_bounds__(256)
proj_kernel(const int* __restrict__ x,
            const float* __restrict__ emb,
            const float* __restrict__ W_ih,
            const float* __restrict__ b_ih)
{
    __shared__ float As[8][128];
    __shared__ float Bs[8][128];
    __shared__ int   idx[128];

    const int tid = threadIdx.x;
    const int m0 = blockIdx.y * 128;
    const int j0 = blockIdx.x * 128;

    if (tid < 128) idx[tid] = x[m0 + tid];
    __syncthreads();

    const int lrow = tid >> 1;
    const int lq   = tid & 1;
    const int ty = tid >> 4;
    const int tx = tid & 15;

    const size_t arow = (size_t)idx[lrow] * HID;
    const size_t brow = (size_t)(j0 + lrow) * HID;

    float acc[8][8];
#pragma unroll
    for (int i = 0; i < 8; ++i)
#pragma unroll
        for (int jc = 0; jc < 8; ++jc) acc[i][jc] = 0.0f;

    float4 av = *(const float4*)(emb  + arow + 4 * lq);
    float4 bv = *(const float4*)(W_ih + brow + 4 * lq);

    for (int k0 = 0; k0 < HID; k0 += 8) {
        As[4*lq+0][lrow] = av.x; As[4*lq+1][lrow] = av.y;
        As[4*lq+2][lrow] = av.z; As[4*lq+3][lrow] = av.w;
        Bs[4*lq+0][lrow] = bv.x; Bs[4*lq+1][lrow] = bv.y;
        Bs[4*lq+2][lrow] = bv.z; Bs[4*lq+3][lrow] = bv.w;
        __syncthreads();

        if (k0 + 8 < HID) {
            av = *(const float4*)(emb  + arow + k0 + 8 + 4 * lq);
            bv = *(const float4*)(W_ih + brow + k0 + 8 + 4 * lq);
        }

#pragma unroll
        for (int k = 0; k < 8; ++k) {
            float a[8], b[8];
            *(float4*)(a)     = *(const float4*)(&As[k][8 * ty]);
            *(float4*)(a + 4) = *(const float4*)(&As[k][8 * ty + 4]);
            *(float4*)(b)     = *(const float4*)(&Bs[k][8 * tx]);
            *(float4*)(b + 4) = *(const float4*)(&Bs[k][8 * tx + 4]);
#pragma unroll
            for (int i = 0; i < 8; ++i)
#pragma unroll
                for (int jc = 0; jc < 8; ++jc)
                    acc[i][jc] += a[i] * b[jc];
        }
        __syncthreads();
    }

    float bi[8];
    *(float4*)(bi)     = *(const float4*)(b_ih + j0 + 8 * tx);
    *(float4*)(bi + 4) = *(const float4*)(b_ih + j0 + 8 * tx + 4);

#pragma unroll
    for (int i = 0; i < 8; ++i) {
        int m = m0 + 8 * ty + i;
        int b = m >> 8;      // T = 256
        int t = m & 255;
        float* dst = &g_xw[((size_t)t * BATCH + b) * HID + j0 + 8 * tx];
        float4 v0, v1;
        v0.x = acc[i][0] + bi[0]; v0.y = acc[i][1] + bi[1];
        v0.z = acc[i][2] + bi[2]; v0.w = acc[i][3] + bi[3];
        v1.x = acc[i][4] + bi[4]; v1.y = acc[i][5] + bi[5];
        v1.z = acc[i][6] + bi[6]; v1.w = acc[i][7] + bi[7];
        *(float4*)(dst)     = v0;
        *(float4*)(dst + 4) = v1;
    }
}

// ---------------------------------------------------------------------------
// Kernel 2: recurrence + FC. 8 clusters x 8 CTAs x 512 threads.
// Each cluster owns 8 batch rows = 2 interleaved groups (A: 0-3, B: 4-7).
// Per step: A segment (wait/compute/reduce/push) then B segment — B's
// compute hides A's st.async flight + mbarrier accounting, and vice versa.
// Per-group structure identical to R10 (best measured): 512 compute threads
// (j2=tid&31, kc=tid>>5), 128 reducers with 8x st.async.b64 each.
// ---------------------------------------------------------------------------
#define RNN_HALF(GRP, T, RB, WB, PHVAR, DOWAIT)                               \
do {                                                                          \
    if (tid == 0) mbar_expect(barA + ((GRP) * 2 + (WB)) * 8, 8192u);          \
    float2 xw2 = make_float2(0.0f, 0.0f);                                     \
    if (tid < 128)                                                            \
        xw2 = *(const float2*)&g_xw[((size_t)(T) * BATCH +                    \
                 (r0 + 4 * (GRP) + rr)) * HID + j0 + 2 * jj2];                \
    if (DOWAIT) { mbar_wait(barA + ((GRP) * 2 + (RB)) * 8, PHVAR);            \
                  PHVAR ^= 1u; }                                              \
    {                                                                         \
        const float* hbase = smemf + (GRP) * 4096 + (RB) * 2048               \
                           + (kc >> 1) * 256 + (kc & 1) * 32;                 \
        float* pbase = smemf + PS_OFF + (GRP) * 4096 + kc * 64 + 2 * j2;      \
        _Pragma("unroll")                                                     \
        for (int r = 0; r < RPC; ++r) {                                       \
            const ulonglong2* hrow = (const ulonglong2*)(hbase + r * 64);     \
            unsigned long long a0 = 0ull, b0 = 0ull, a1 = 0ull, b1 = 0ull;    \
            _Pragma("unroll")                                                 \
            for (int q = 0; q < 8; ++q) {                                     \
                ulonglong2 hv = hrow[q];                                      \
                a0 = fma2(hv.x, wp0[2*q],   a0);                              \
                b0 = fma2(hv.y, wp0[2*q+1], b0);                              \
                a1 = fma2(hv.x, wp1[2*q],   a1);                              \
                b1 = fma2(hv.y, wp1[2*q+1], b1);                              \
            }                                                                 \
            *(float2*)(pbase + r * 1024) =                                    \
                make_float2(f32x2_hsum(a0, b0), f32x2_hsum(a1, b1));          \
        }                                                                     \
    }                                                                         \
    __syncthreads();                                                          \
    if (tid < 128) {                                                          \
        const float* rbase = smemf + PS_OFF + (GRP) * 4096 + rr * 1024        \
                           + 2 * jj2;                                         \
        float z0 = bhh2.x + xw2.x;                                            \
        float z1 = bhh2.y + xw2.y;                                            \
        _Pragma("unroll")                                                     \
        for (int c = 0; c < 16; ++c) {                                        \
            float2 pv = *(const float2*)(rbase + c * 64);                     \
            z0 += pv.x; z1 += pv.y;                                           \
        }                                                                     \
        const unsigned long long hpk =                                        \
            pack2(tanh_accurate(z0), tanh_accurate(z1));                      \
        const uint32_t loff = hsAaddr +                                       \
            (uint32_t)((GRP) * 4096 + (WB) * 2048 + rank * 256 + rr * 64      \
                       + 2 * jj2) * 4u;                                       \
        const uint32_t lbar = barA + ((GRP) * 2 + (WB)) * 8;                  \
        _Pragma("unroll")                                                     \
        for (int c = 0; c < CLUSTER; ++c)                                     \
            st_async_b64(mapa32(loff, c), hpk, mapa32(lbar, c));              \
    }                                                                         \
} while (0)

__global__ void __cluster_dims__(CLUSTER, 1, 1) __launch_bounds__(512, 1)
rec_kernel(const float* __restrict__ W_hh,
           const float* __restrict__ b_hh,
           const float* __restrict__ W_fc,
           const float* __restrict__ b_fc,
           float* __restrict__ out)
{
    extern __shared__ __align__(16) float smemf[];

    const int tid  = threadIdx.x;
    const int rank = blockIdx.x & (CLUSTER - 1);
    const int cl   = blockIdx.x / CLUSTER;
    const int r0 = cl * (RPC * GROUPS);          // 8 rows per cluster
    const int j0 = rank * CPC;

    const int j2  = tid & 31;          // compute: column pair (cols 2j2, 2j2+1)
    const int kc  = tid >> 5;          // compute: 32-wide k chunk (0..15)
    const int rr  = tid >> 5;          // reduce (tid<128): row 0..3
    const int jj2 = tid & 31;          // reduce: column pair

    const uint32_t hsAaddr = smem_u32(smemf);
    const uint32_t barA    = hsAaddr + 16384u * 4u;

    // W_hh slices for 2 columns, packed as f32x2 k-pairs (16 u64 each).
    // Shared by both batch groups.
    unsigned long long wp0[16], wp1[16];
    {
        const float* w0 = W_hh + (size_t)(j0 + 2 * j2)     * HID + kc * 32;
        const float* w1 = W_hh + (size_t)(j0 + 2 * j2 + 1) * HID + kc * 32;
#pragma unroll
        for (int q = 0; q < 8; ++q) {
            ulonglong2 v0 = *(const ulonglong2*)(w0 + 4 * q);
            ulonglong2 v1 = *(const ulonglong2*)(w1 + 4 * q);
            wp0[2*q] = v0.x; wp0[2*q+1] = v0.y;
            wp1[2*q] = v1.x; wp1[2*q+1] = v1.y;
        }
    }
    float2 bhh2 = make_float2(0.0f, 0.0f);
    if (tid < 128) bhh2 = *(const float2*)&b_hh[j0 + 2 * jj2];

    // Init: 4 mbarriers (grp x buf, 1 arrival each) + hs = 0 (both groups).
    if (tid == 0) {
#pragma unroll
        for (int i = 0; i < 4; ++i) mbar_init(barA + i * 8, 1u);
    }
    for (int i = tid; i < 8192; i += 512) smemf[i] = 0.0f;
    __syncthreads();
    // Peers' barriers must be initialized before any st.async reaches them.
    asm volatile("barrier.cluster.arrive.aligned;" ::: "memory");
    asm volatile("barrier.cluster.wait.aligned;"   ::: "memory");

    uint32_t phA0 = 0, phA1 = 0, phB0 = 0, phB1 = 0;

    // Step 1: both groups read local zeros (no wait), write buf1.
    RNN_HALF(0, 0, 0, 1, phA1, false);
    RNN_HALF(1, 0, 0, 1, phB1, false);
    // Step 2: wait buf1, write buf0.
    RNN_HALF(0, 1, 1, 0, phA1, true);
    RNN_HALF(1, 1, 1, 0, phB1, true);
    // Steps 3..256 in pairs.
#pragma unroll 1
    for (int q = 1; q < 128; ++q) {
        RNN_HALF(0, 2 * q,     0, 1, phA0, true);
        RNN_HALF(1, 2 * q,     0, 1, phB0, true);
        RNN_HALF(0, 2 * q + 1, 1, 0, phA1, true);
        RNN_HALF(1, 2 * q + 1, 1, 0, phB1, true);
    }

    // Consume the step-256 pushes (buffer 0, both groups).
    mbar_wait(barA + 0 * 8, phA0);
    mbar_wait(barA + 2 * 8, phB0);

    // FC: h_T in buf 0 of each group.
    // 32 tasks (8 rows x 4 outs) over 16 warps, 2 tasks per warp.
    if (rank == 0) {
        const int w    = tid >> 5;
        const int lane = tid & 31;
#pragma unroll
        for (int t = w; t < 32; t += 16) {
            const int r = t >> 2;          // local row 0..7
            const int o = t & 3;
            const int grp = r >> 2;
            const int row = r & 3;
            const float* hb = smemf + grp * 4096 + row * 64;  // + (k>>6)*256
            const float* wf = W_fc + (size_t)o * HID;
            float s = 0.0f;
#pragma unroll
            for (int k = lane; k < HID; k += 32)
                s += hb[(k >> 6) * 256 + (k & 63)] * wf[k];
#pragma unroll
            for (int sh = 16; sh > 0; sh >>= 1)
                s += __shfl_xor_sync(0xFFFFFFFFu, s, sh);
            if (lane == 0)
                out[(r0 + r) * OUTD + o] = s + b_fc[o];
        }
    }

    // Cluster-wide quiesce before exit (DSMEM lifetime).
    asm volatile("barrier.cluster.arrive.aligned;" ::: "memory");
    asm volatile("barrier.cluster.wait.aligned;"   ::: "memory");
}

extern "C" void kernel_launch(void* const* d_in, const int* in_sizes, int n_in,
                              void* d_out, int out_size)
{
    const int*   x    = (const int*)  d_in[0];
    const float* emb  = (const float*)d_in[1];
    const float* W_ih = (const float*)d_in[2];
    const float* W_hh = (const float*)d_in[3];
    const float* b_ih = (const float*)d_in[4];
    const float* b_hh = (const float*)d_in[5];
    const float* W_fc = (const float*)d_in[6];
    const float* b_fc = (const float*)d_in[7];
    float* out = (float*)d_out;
    (void)in_sizes; (void)n_in; (void)out_size;

    cudaFuncSetAttribute(rec_kernel,
                         cudaFuncAttributeMaxDynamicSharedMemorySize,
                         SMEM_BYTES);

    proj_kernel<<<dim3(HID / 128, (BATCH * T_STEPS) / 128), 256>>>(x, emb, W_ih, b_ih);
    rec_kernel<<<(BATCH / (RPC * GROUPS)) * CLUSTER, 512, SMEM_BYTES>>>(
        W_hh, b_hh, W_fc, b_fc, out);
}